// round 3
// baseline (speedup 1.0000x reference)
#include <cuda_runtime.h>
#include <stdint.h>
#include <math.h>

// Problem constants (fixed instance: n=5003, K=3, k=1, num_sample=100)
#define NN      5003
#define NSAMPLE 100
#define KSEL    1
#define TPB     512
#define NWARP   (TPB / 32)
#define NITER   ((NN + TPB - 1) / TPB)   // 10
#define VCAP    2048
#define TINYF   1.17549435e-38f

// prep kernel layout
#define ZBLK   1024
#define CS_X   20
#define CS_Y   16
#define ROWS_PER ((NN + CS_Y - 1) / CS_Y)   // 313
#define LOGZ_B 20

// Survivor-filter tier thresholds in 23-bit mantissa space (conservative,
// value itself re-evaluated on device; constants only pick the tier).
#define U_A 8162787u   // ~ g >= 3.6
#define U_B 7981470u   // ~ g >= 3.0
#define U_C 7327025u   // ~ g >= 2.0

__device__ double g_part[CS_Y][NN];
__device__ float  g_logZ[NN];
__device__ double g_logp;
__device__ int    g_lzmin_i, g_lzmax_i;   // float bits (logZ > 0 -> int order ok)

// ---------------------------------------------------------------------------
// threefry2x32, key = (0, 42); partitionable mode: bits = o0 ^ o1 @ ctr (0, i)
// ---------------------------------------------------------------------------
__device__ __forceinline__ uint32_t threefry_bits(uint32_t idx) {
  uint32_t x0 = 0u, x1 = idx;
  const uint32_t ks0 = 0u;
  const uint32_t ks1 = 42u;
  const uint32_t ks2 = 0x1BD11BDAu ^ ks0 ^ ks1;
#define TF_R(r) { x0 += x1; x1 = __funnelshift_l(x1, x1, (r)); x1 ^= x0; }
  x0 += ks0; x1 += ks1;
  TF_R(13) TF_R(15) TF_R(26) TF_R(6)
  x0 += ks1; x1 += ks2 + 1u;
  TF_R(17) TF_R(29) TF_R(16) TF_R(24)
  x0 += ks2; x1 += ks0 + 2u;
  TF_R(13) TF_R(15) TF_R(26) TF_R(6)
  x0 += ks0; x1 += ks1 + 3u;
  TF_R(17) TF_R(29) TF_R(16) TF_R(24)
  x0 += ks1; x1 += ks2 + 4u;
  TF_R(13) TF_R(15) TF_R(26) TF_R(6)
  x0 += ks2; x1 += ks0 + 5u;
#undef TF_R
  return x0 ^ x1;
}

// gumbel from mantissa (23-bit) — must stay bit-identical to prior rounds
__device__ __forceinline__ float gumbel_from_mant(uint32_t mant) {
  uint32_t fb = mant | 0x3F800000u;
  float f = __uint_as_float(fb) - 1.0f;             // exact
  float u = fmaxf(TINYF, __fadd_rn(f, TINYF));
  return -__logf(-__logf(u));
}

// ---------------------------------------------------------------------------
// k_prep: zero C, colsum partials (no atomics), misc init
// ---------------------------------------------------------------------------
__global__ void k_prep(float *__restrict__ out, size_t total,
                       const float *__restrict__ Bk) {
  int bid = blockIdx.x;
  int tid = threadIdx.x;
  if (bid < ZBLK) {
    size_t i = (size_t)bid * blockDim.x + tid;
    size_t stride = (size_t)ZBLK * blockDim.x;
    size_t nv4 = total >> 2;
    float4 *o4 = (float4 *)out;
    float4 z4 = make_float4(0.f, 0.f, 0.f, 0.f);
    for (size_t j = i; j < nv4; j += stride) o4[j] = z4;
    for (size_t j = (nv4 << 2) + i; j < total; j += stride) out[j] = 0.0f;
  } else if (bid < ZBLK + CS_X * CS_Y) {
    int cb = bid - ZBLK;
    int cx = cb % CS_X;
    int cy = cb / CS_X;
    int c = cx * 256 + tid;
    if (tid < 256 && c < NN) {
      int r0 = cy * ROWS_PER;
      int r1 = min(r0 + ROWS_PER, NN);
      float a0 = 0.f, a1 = 0.f, a2 = 0.f, a3 = 0.f;
      int r = r0;
      for (; r + 3 < r1; r += 4) {
        a0 += __expf(Bk[(size_t)(r + 0) * NN + c]);
        a1 += __expf(Bk[(size_t)(r + 1) * NN + c]);
        a2 += __expf(Bk[(size_t)(r + 2) * NN + c]);
        a3 += __expf(Bk[(size_t)(r + 3) * NN + c]);
      }
      for (; r < r1; r++) a0 += __expf(Bk[(size_t)r * NN + c]);
      g_part[cy][c] = (double)((a0 + a1) + (a2 + a3));
    }
  } else {
    if (tid == 0) {
      g_lzmin_i = 0x7F800000;   // +inf
      g_lzmax_i = 0;
      g_logp = 0.0;
    }
  }
}

// ---------------------------------------------------------------------------
// k_mid: logZ (+min/max) in blocks [0, LOGZ_B), edge scatter after
// ---------------------------------------------------------------------------
__global__ void k_mid(const int *__restrict__ ei, int ne, float *__restrict__ C) {
  int bid = blockIdx.x;
  int tid = threadIdx.x;
  if (bid < LOGZ_B) {
    int c = bid * 256 + tid;
    if (c < NN) {
      double s = 0.0;
      #pragma unroll
      for (int k = 0; k < CS_Y; k++) s += g_part[k][c];
      float lz = logf((float)s);
      g_logZ[c] = lz;
      atomicMin(&g_lzmin_i, __float_as_int(lz));
      atomicMax(&g_lzmax_i, __float_as_int(lz));
    }
  } else {
    int e = (bid - LOGZ_B) * 256 + tid;
    if (e < ne) {
      int s = ei[e];
      int d = ei[ne + e];
      C[(size_t)s * NN + d] = 1.0f;
    }
  }
}

// warp-parallel descending bin select over hist[256]: sets sh_d, updates sh_need
#define BIN_SELECT()                                                         \
  if (tid < 32) {                                                            \
    int b0 = 255 - 8 * tid;                                                  \
    unsigned int psum = 0;                                                   \
    _Pragma("unroll")                                                        \
    for (int i = 0; i < 8; i++) psum += hist[b0 - i];                        \
    unsigned int pre = psum;                                                 \
    _Pragma("unroll")                                                        \
    for (int off = 1; off < 32; off <<= 1) {                                 \
      unsigned int v = __shfl_up_sync(0xFFFFFFFFu, pre, off);                \
      if (tid >= off) pre += v;                                              \
    }                                                                        \
    unsigned int excl = pre - psum;                                          \
    int need = sh_need;                                                      \
    __syncwarp();                                                            \
    if ((int)excl < need && (int)(excl + psum) >= need) {                    \
      unsigned int cum = excl;                                               \
      _Pragma("unroll")                                                      \
      for (int i = 0; i < 8; i++) {                                          \
        unsigned int h = hist[b0 - i];                                       \
        if ((int)(cum + h) >= need) {                                        \
          sh_d = b0 - i; sh_need = need - (int)cum; break;                   \
        }                                                                    \
        cum += h;                                                            \
      }                                                                      \
    }                                                                        \
  }                                                                          \
  __syncthreads();

// ---------------------------------------------------------------------------
// k_topk: per-row exact top-NSAMPLE with bits-monotone survivor pre-filter
// ---------------------------------------------------------------------------
__global__ __launch_bounds__(TPB) void k_topk(const float *__restrict__ Bk,
                                              float *__restrict__ C) {
  __shared__ uint32_t bits[NN];                 // raw threefry bits / overlay keys
  __shared__ uint32_t vkey[VCAP];
  __shared__ unsigned short cand[VCAP];
  __shared__ unsigned int hist[256];
  __shared__ double warpsum[NWARP];
  __shared__ int sh_nA, sh_nB, sh_nC, sh_m, sh_need, sh_d;
  __shared__ uint32_t sh_cutm, sh_pref;

  const int r = blockIdx.x;
  const int tid = threadIdx.x;
  const int lane = tid & 31;
  const uint32_t base = (uint32_t)r * (uint32_t)NN;

  if (tid == 0) {
    sh_nA = 0; sh_nB = 0; sh_nC = 0; sh_m = 0;
    sh_need = NSAMPLE; sh_pref = 0u;
  }
  __syncthreads();

  // ---- pass 1: threefry bits + tier witness counts (ballot, no logs) ----
  unsigned cntA = 0, cntB = 0, cntC = 0;
  #pragma unroll 2
  for (int j = 0; j < NITER; j++) {
    int c = tid + j * TPB;
    uint32_t bb = 0;
    if (c < NN) {
      bb = threefry_bits(base + (uint32_t)c);
      bits[c] = bb;
    }
    uint32_t bu = bb >> 9;
    bool inb = (c < NN);
    unsigned ma = __ballot_sync(0xFFFFFFFFu, inb && bu >= U_A);
    unsigned mb = __ballot_sync(0xFFFFFFFFu, inb && bu >= U_B);
    unsigned mc = __ballot_sync(0xFFFFFFFFu, inb && bu >= U_C);
    if (lane == 0) { cntA += __popc(ma); cntB += __popc(mb); cntC += __popc(mc); }
  }
  if (lane == 0) {
    atomicAdd(&sh_nA, (int)cntA);
    atomicAdd(&sh_nB, (int)cntB);
    atomicAdd(&sh_nC, (int)cntC);
  }
  __syncthreads();

  // ---- tier pick + conservative mantissa cut (thread 0) ----
  if (tid == 0) {
    uint32_t Ut = 0;
    if (sh_nA >= NSAMPLE) Ut = U_A;
    else if (sh_nB >= NSAMPLE) Ut = U_B;
    else if (sh_nC >= NSAMPLE) Ut = U_C;
    uint32_t cutm = 0;
    if (Ut != 0) {
      float gke = gumbel_from_mant(Ut);   // >=100 elements have g >= gke
      float lzmin = __int_as_float(g_lzmin_i);
      float lzmax = __int_as_float(g_lzmax_i);
      float gcut = gke - (1.0f + (lzmax - lzmin) + 1e-3f);
      double uc = exp(-exp(-(double)gcut));
      double cm = floor(uc * 8388608.0) - 256.0;   // down-rounded margin
      cutm = (cm < 1.0) ? 0u : (uint32_t)cm;
    }
    sh_cutm = cutm;
  }
  __syncthreads();
  const uint32_t cutm = sh_cutm;

  // ---- survivor compaction + v-key build (logs only for survivors) ----
  if (cutm != 0) {
    #pragma unroll 2
    for (int j = 0; j < NITER; j++) {
      int c = tid + j * TPB;
      uint32_t bb = (c < NN) ? bits[c] : 0u;
      bool p = (c < NN) && ((bb >> 9) >= cutm);
      unsigned mask = __ballot_sync(0xFFFFFFFFu, p);
      if (mask) {
        int leader = __ffs(mask) - 1;
        int posbase = 0;
        if (lane == leader) posbase = atomicAdd(&sh_m, __popc(mask));
        posbase = __shfl_sync(0xFFFFFFFFu, posbase, leader);
        if (p) {
          int pos = posbase + __popc(mask & ((1u << lane) - 1u));
          if (pos < VCAP) {
            float b = Bk[base + (uint32_t)c];
            float g = gumbel_from_mant(bb >> 9);
            float v = __fadd_rn(__fsub_rn(b, g_logZ[c]), g);
            uint32_t fb = __float_as_uint(v);
            fb = (fb & 0x80000000u) ? ~fb : (fb | 0x80000000u);
            vkey[pos] = fb;
            cand[pos] = (unsigned short)c;
          }
        }
      }
    }
  }
  __syncthreads();

  const bool full = (cutm == 0) || (sh_m > VCAP);
  int mm;
  if (full) {
    // overlay: every element is a candidate; rewrite bits[] in place as v-keys
    for (int c = tid; c < NN; c += TPB) {
      uint32_t bb = bits[c];
      float b = Bk[base + (uint32_t)c];
      float g = gumbel_from_mant(bb >> 9);
      float v = __fadd_rn(__fsub_rn(b, g_logZ[c]), g);
      uint32_t fb = __float_as_uint(v);
      fb = (fb & 0x80000000u) ? ~fb : (fb | 0x80000000u);
      bits[c] = fb;
    }
    mm = NN;
    __syncthreads();
  } else {
    mm = sh_m;
  }

#define SKEY(i) (full ? bits[i] : vkey[i])
#define SORIG(i) (full ? (i) : (int)cand[i])

  // ---- 4-pass radix select over the mm candidates ----
  const int miters = (mm + TPB - 1) / TPB;
  for (int shift = 24; shift >= 0; shift -= 8) {
    if (tid < 256) hist[tid] = 0u;
    __syncthreads();
    uint32_t pref = sh_pref;
    int hs = shift + 8;
    for (int j = 0; j < miters; j++) {
      int i = tid + j * TPB;
      unsigned int bin = 0xFFFFu;
      if (i < mm) {
        uint32_t kk = SKEY(i);
        if (hs >= 32 || (kk >> hs) == (pref >> hs))
          bin = (kk >> shift) & 255u;
      }
      unsigned int mmk = __match_any_sync(0xFFFFFFFFu, bin);
      if ((int)(__ffs(mmk) - 1) == lane && bin < 256u)
        atomicAdd(&hist[bin], __popc(mmk));
    }
    __syncthreads();
    BIN_SELECT();
    if (tid == 0) sh_pref |= ((uint32_t)sh_d << shift);
    __syncthreads();
  }
  const uint32_t T = sh_pref;
  const int need_eq = sh_need;   // how many key==T elements to take

  // ---- epilogue: flips + log_p ----
  double local = 0.0;
  for (int i = tid; i < mm; i += TPB) {
    uint32_t kk = SKEY(i);
    if (kk > T) {
      int c = SORIG(i);
      size_t idx = (size_t)c * NN + r;     // flip C[c, r], acc Bk[c, r]
      local += (double)Bk[idx];
      C[idx] = 1.0f - C[idx];
    }
  }
  // ties at T: lowest original index first
  for (int i = tid; i < mm; i += TPB) {
    if (SKEY(i) == T) {
      int c = SORIG(i);
      int rank = 0;
      for (int j = 0; j < mm; j++)
        rank += (SKEY(j) == T && SORIG(j) < c);
      if (rank < need_eq) {
        size_t idx = (size_t)c * NN + r;
        local += (double)Bk[idx];
        C[idx] = 1.0f - C[idx];
      }
    }
  }

  #pragma unroll
  for (int off = 16; off; off >>= 1)
    local += __shfl_down_sync(0xFFFFFFFFu, local, off);
  if (lane == 0) warpsum[tid >> 5] = local;
  __syncthreads();
  if (tid == 0) {
    double t = 0.0;
    #pragma unroll
    for (int w = 0; w < NWARP; w++) t += warpsum[w];
    atomicAdd(&g_logp, t - (double)g_logZ[r]);
  }
#undef SKEY
#undef SORIG
}

__global__ void k_final(float *__restrict__ out, size_t pos) {
  if (threadIdx.x == 0) out[pos] = (float)g_logp;
}

// ---------------------------------------------------------------------------
// Launch
// ---------------------------------------------------------------------------
extern "C" void kernel_launch(void *const *d_in, const int *in_sizes, int n_in,
                              void *d_out, int out_size) {
  const int   *ei = (const int *)d_in[0];     // edge_index [2, n_edges] int32
  const float *B  = (const float *)d_in[1];   // B [K, n, n] float32
  const int ne = in_sizes[0] / 2;
  const float *Bk = B + (size_t)KSEL * NN * NN;
  float *out = (float *)d_out;
  const size_t total = (size_t)out_size;

  k_prep<<<ZBLK + CS_X * CS_Y + 1, 256>>>(out, total, Bk);

  const int eb = (ne + 255) / 256;
  k_mid<<<LOGZ_B + eb, 256>>>(ei, ne, out);

  k_topk<<<NN, TPB>>>(Bk, out);

  const size_t pos = (size_t)NN * NN;
  if (pos < total) k_final<<<1, 32>>>(out, pos);
}